// round 16
// baseline (speedup 1.0000x reference)
#include <cuda_runtime.h>
#include <cuda_fp16.h>
#include <cstdint>

// WeightedConvTranspose via mma.sync (fp16 m16n8k16, fp32 accum).
// R16 = R15 + sync restructure (3 -> 2 barriers/tile) + swizzle hoisting:
//   - issue_cp(next) moved after the post-wait barrier -> end-of-tile sync
//     provably removable with single XH/we buffers
//   - swz128(base + kb) == swz128(base) ^ kb (kb bits 5-6; base bits 5-6 clear):
//     per-toff/tap swizzled bases precomputed, XOR per k16

#define B_       8
#define NIN_     16384
#define LOUT_    32768
#define PT_      128
#define THREADS_ 512
#define TILES_   (B_ * (NIN_ / PT_))   // 1024

#define XSP_     134                    // x stage pitch (floats), conflict-free transpose
#define CSP_     264

// ---- SMEM layout (bytes) ----
#define OFF_W    0                      // 9 chunks x 8192 (fp16 W) = 73728
#define WCH_(j)  (OFF_W + (j) * 8192)
#define OFF_XHI  73728                  // XH: 132 rows x 128B = 16896 (single buffer)
#define OFF_XS   90624                  // 2 bufs x 64*134*4 = 2 x 34304
#define OFF_CSB  159232                 // 2 bufs x 3*264*4  = 2 x 3168
#define OFF_WE   165568                 // 9*128*4 = 4608 (single buffer)
#define SMEM_BYTES 170176

static __device__ __forceinline__ uint32_t smem_u32(const void* p) {
    uint32_t a;
    asm("{ .reg .u64 t; cvta.to.shared.u64 t, %1; cvt.u32.u64 %0, t; }" : "=r"(a) : "l"(p));
    return a;
}
static __device__ __forceinline__ uint32_t swz128(uint32_t off) {
    return off ^ ((off >> 3) & 0x70);
}
static __device__ __forceinline__ uint32_t cvt_f16x2(float a, float b) {
    uint32_t r;
    asm("cvt.rn.f16x2.f32 %0, %1, %2;" : "=r"(r) : "f"(b), "f"(a));
    return r;
}
static __device__ __forceinline__ uint32_t hmul2u(uint32_t a, uint32_t w) {
    uint32_t r;
    asm("mul.rn.f16x2 %0, %1, %2;" : "=r"(r) : "r"(a), "r"(w));
    return r;
}
static __device__ __forceinline__ void ldsm_x4(uint32_t* r, uint32_t addr) {
    asm volatile("ldmatrix.sync.aligned.m8n8.x4.shared.b16 {%0,%1,%2,%3}, [%4];"
                 : "=r"(r[0]), "=r"(r[1]), "=r"(r[2]), "=r"(r[3]) : "r"(addr));
}
static __device__ __forceinline__ void mma_f16(float* d, const uint32_t* a,
                                               uint32_t b0, uint32_t b1) {
    asm volatile("mma.sync.aligned.m16n8k16.row.col.f32.f16.f16.f32 "
                 "{%0,%1,%2,%3}, {%4,%5,%6,%7}, {%8,%9}, {%0,%1,%2,%3};"
                 : "+f"(d[0]), "+f"(d[1]), "+f"(d[2]), "+f"(d[3])
                 : "r"(a[0]), "r"(a[1]), "r"(a[2]), "r"(a[3]), "r"(b0), "r"(b1));
}
static __device__ __forceinline__ void cp8(uint32_t dst, const float* src, int valid) {
    asm volatile("cp.async.ca.shared.global [%0], [%1], 8, %2;"
                 :: "r"(dst), "l"(src), "r"(valid) : "memory");
}
static __device__ __forceinline__ void cp8f(uint32_t dst, const float* src) {
    asm volatile("cp.async.ca.shared.global [%0], [%1], 8;"
                 :: "r"(dst), "l"(src) : "memory");
}
static __device__ __forceinline__ void cp16(uint32_t dst, const float* src, int valid) {
    asm volatile("cp.async.ca.shared.global [%0], [%1], 16, %2;"
                 :: "r"(dst), "l"(src), "r"(valid) : "memory");
}
static __device__ __forceinline__ void cp16f(uint32_t dst, const float* src) {
    asm volatile("cp.async.ca.shared.global [%0], [%1], 16;"
                 :: "r"(dst), "l"(src) : "memory");
}

__global__ void __launch_bounds__(THREADS_, 1)
wct_mma_kernel(const float* __restrict__ x, const float* __restrict__ coords,
               const float* __restrict__ sigma, const float* __restrict__ weight,
               float* __restrict__ out) {
    extern __shared__ char smem[];
    const uint32_t sb = smem_u32(smem);
    const int tid  = threadIdx.x;
    const int wid  = tid >> 5;
    const int lane = tid & 31;

    float* we_s = (float*)(smem + OFF_WE);

    // ---- one-time W (single fp16): chunk j = W[o][c] for tap j, SW128 rows ----
    for (int idx = tid; idx < 64 * 64 * 9; idx += THREADS_) {
        int j  = idx % 9;
        int oc = idx / 9;
        int c  = oc & 63;
        int o  = oc >> 6;
        __half h = __float2half_rn(weight[oc * 9 + j]);
        uint32_t bo = swz128((uint32_t)o * 128 + (uint32_t)c * 2);
        *(__half*)(smem + WCH_(j) + bo) = h;
    }
    const float rsig = 1.0f / sigma[0];

    // warp tile: 16 warps = 4 p-groups (32p) x 4 o-groups (16o), both parities
    const int on  = wid & 3;
    const int pg  = wid >> 2;
    const int pbase = pg * 32;
    const int obase = on * 16;
    const int prow  = pbase + (lane >> 2);

    const uint32_t a_ro0 = (uint32_t)(pbase + (lane & 15)) * 128 + (uint32_t)(lane >> 4) * 16;
    const uint32_t a_ro1 = a_ro0 + 16 * 128;
    const uint32_t b_ro  = (uint32_t)(obase + (lane & 15)) * 128 + (uint32_t)(lane >> 4) * 16;
    const uint32_t sw_b  = swz128(b_ro);     // toff-invariant; ^kb per k16

    // phase-2 convert lane mapping
    const int bp  = wid * 8 + (lane >> 2);
    const int bc0 = lane & 3;

    // ---- cp.async issue for one tile into buffer 'buf' ----
    auto issue_cp = [&](int ti, int buf) {
        const int b  = ti >> 7;
        const int p0 = (ti & 127) * PT_;
        const uint32_t xsd = sb + OFF_XS + (uint32_t)buf * 34304u;
        const uint32_t csd = sb + OFF_CSB + (uint32_t)buf * 3168u;
        const float* xb = x + (size_t)b * 64 * NIN_ + (p0 - 2);
        const float* cb = coords + (size_t)b * 3 * LOUT_ + (2 * p0 - 4);
        if (p0 >= 2 && p0 <= NIN_ - 132) {
            #pragma unroll 1
            for (int idx = tid; idx < 64 * 66; idx += THREADS_) {
                int c  = idx / 66;
                int ch = idx - c * 66;
                cp8f(xsd + (uint32_t)(c * XSP_ + 2 * ch) * 4u, xb + (size_t)c * NIN_ + 2 * ch);
            }
            for (int idx = tid; idx < 3 * 66; idx += THREADS_) {
                int d  = idx / 66;
                int ch = idx - d * 66;
                cp16f(csd + (uint32_t)(d * CSP_ + 4 * ch) * 4u, cb + (size_t)d * LOUT_ + 4 * ch);
            }
        } else {
            for (int idx = tid; idx < 64 * 66; idx += THREADS_) {
                int c  = idx / 66;
                int ch = idx - c * 66;
                int xi0 = 2 * ch;
                int g0  = p0 - 2 + xi0;
                int rem = NIN_ - g0;
                int valid = (g0 < 0) ? 0 : (rem >= 2 ? 8 : (rem == 1 ? 4 : 0));
                int gc  = g0 < 0 ? 0 : (g0 > NIN_ - 2 ? NIN_ - 2 : g0);
                cp8(xsd + (uint32_t)(c * XSP_ + xi0) * 4u,
                    x + (size_t)b * 64 * NIN_ + (size_t)c * NIN_ + gc, valid);
            }
            for (int idx = tid; idx < 3 * 66; idx += THREADS_) {
                int d  = idx / 66;
                int ch = idx - d * 66;
                int k0 = 4 * ch;
                int g0 = 2 * p0 - 4 + k0;
                int rem = LOUT_ - g0;
                int valid = (g0 < 0) ? 0 : (rem >= 4 ? 16 : (rem > 0 ? rem * 4 : 0));
                int gc = g0 < 0 ? 0 : (g0 > LOUT_ - 4 ? LOUT_ - 4 : g0);
                cp16(csd + (uint32_t)(d * CSP_ + k0) * 4u,
                     coords + (size_t)b * 3 * LOUT_ + (size_t)d * LOUT_ + gc, valid);
            }
        }
    };

    __syncthreads();  // W ready

    if ((int)blockIdx.x < TILES_) issue_cp(blockIdx.x, 0);
    asm volatile("cp.async.commit_group;" ::: "memory");

    int it = 0;
    for (int ti = blockIdx.x; ti < TILES_; ti += gridDim.x, ++it) {
        const int buf = it & 1;
        const int b   = ti >> 7;
        const int p0  = (ti & 127) * PT_;
        const int nxt = ti + gridDim.x;

        asm volatile("cp.async.wait_group 0;" ::: "memory");  // cp(ti) done (only group in flight)
        __syncthreads();   // everyone's cp(ti) visible; all reads of prior buffers complete

        // issue next tile AFTER the barrier: xs[buf^1]'s previous readers
        // (convert(it-1)) are guaranteed past by the barrier above.
        if (nxt < TILES_) {
            issue_cp(nxt, buf ^ 1);
            asm volatile("cp.async.commit_group;" ::: "memory");
        }

        float* xsB  = (float*)(smem + OFF_XS + (uint32_t)buf * 34304u);
        float* cs_s = (float*)(smem + OFF_CSB + (uint32_t)buf * 3168u);

        // ---- phase 2: convert x[c][xi] -> XH[xi][c] fp16 (SW128), compute we ----
        {
            const uint32_t m = ((uint32_t)bp & 7) << 4;
            char* hbase = smem + OFF_XHI + bp * 128;
            #pragma unroll
            for (int rr = 0; rr < 4; ++rr) {
                int c0 = bc0 * 4 + rr * 16;
                float a0 = xsB[(c0 + 0) * XSP_ + bp];
                float a1 = xsB[(c0 + 1) * XSP_ + bp];
                float a2 = xsB[(c0 + 2) * XSP_ + bp];
                float a3 = xsB[(c0 + 3) * XSP_ + bp];
                uint32_t h0 = cvt_f16x2(a0, a1);
                uint32_t h1 = cvt_f16x2(a2, a3);
                uint32_t d = ((uint32_t)c0 * 2) ^ m;
                *(uint2*)(hbase + d) = make_uint2(h0, h1);
            }
            if (tid < 64) {                            // tail rows 128..131
                int row = 128 + (tid >> 4);
                int c0  = (tid & 15) * 4;
                const uint32_t m2 = ((uint32_t)row & 7) << 4;
                float a0 = xsB[(c0 + 0) * XSP_ + row];
                float a1 = xsB[(c0 + 1) * XSP_ + row];
                float a2 = xsB[(c0 + 2) * XSP_ + row];
                float a3 = xsB[(c0 + 3) * XSP_ + row];
                uint32_t h0 = cvt_f16x2(a0, a1);
                uint32_t h1 = cvt_f16x2(a2, a3);
                uint32_t d = ((uint32_t)c0 * 2) ^ m2;
                *(uint2*)(smem + OFF_XHI + row * 128 + d) = make_uint2(h0, h1);
            }
        }
        // radial weights we[j][p] for l = 2p + (j&1)
        for (int idx = tid; idx < 9 * 128; idx += THREADS_) {
            int j = idx >> 7;
            int p = idx & 127;
            int pr = j & 1;
            int kt = 2 * p + pr + j;
            int kc = 2 * p + pr + 4;
            float dx = cs_s[kt] - cs_s[kc];
            float dy = cs_s[CSP_ + kt] - cs_s[CSP_ + kc];
            float dz = cs_s[2 * CSP_ + kt] - cs_s[2 * CSP_ + kc];
            float nn = sqrtf(fmaf(dx, dx, fmaf(dy, dy, dz * dz)));
            we_s[idx] = fmaxf(1.0f - nn * rsig, 0.0f);
        }
        __syncthreads();

        // ---- phase 3: toff loop; tap pair (2t-1, 2t) shares A-fragments ----
        float accE[16], accO[16];
        #pragma unroll
        for (int i = 0; i < 16; ++i) { accE[i] = 0.0f; accO[i] = 0.0f; }

        const uint32_t xhi_b = sb + OFF_XHI;

        // peel toff = 0 (even tap j=0 only)
        {
            const float* wj = we_s;                    // j = 0
            uint32_t w0 = cvt_f16x2(wj[prow],      wj[prow]);
            uint32_t w1 = cvt_f16x2(wj[prow + 8],  wj[prow + 8]);
            uint32_t w2 = cvt_f16x2(wj[prow + 16], wj[prow + 16]);
            uint32_t w3 = cvt_f16x2(wj[prow + 24], wj[prow + 24]);
            const uint32_t wchE = sb + (uint32_t)WCH_(0);
            const uint32_t swA0 = swz128(a_ro0);
            const uint32_t swA1 = swz128(a_ro1);
            #pragma unroll
            for (int k16 = 0; k16 < 4; ++k16) {
                const uint32_t kb = (uint32_t)k16 * 32;
                uint32_t a0[4], a1[4], be[4], s[4];
                ldsm_x4(a0, xhi_b + (swA0 ^ kb));
                ldsm_x4(a1, xhi_b + (swA1 ^ kb));
                ldsm_x4(be, wchE + (sw_b ^ kb));
                s[0] = hmul2u(a0[0], w0); s[2] = hmul2u(a0[2], w0);
                s[1] = hmul2u(a0[1], w1); s[3] = hmul2u(a0[3], w1);
                mma_f16(accE + 0, s, be[0], be[2]);
                mma_f16(accE + 4, s, be[1], be[3]);
                s[0] = hmul2u(a1[0], w2); s[2] = hmul2u(a1[2], w2);
                s[1] = hmul2u(a1[1], w3); s[3] = hmul2u(a1[3], w3);
                mma_f16(accE + 8,  s, be[0], be[2]);
                mma_f16(accE + 12, s, be[1], be[3]);
            }
        }

        #pragma unroll 1
        for (int toff = 1; toff < 5; ++toff) {
            const int jE = 2 * toff;        // even tap
            const int jO = 2 * toff - 1;    // odd tap (same toff)
            const uint32_t wchE = sb + (uint32_t)WCH_(jE);
            const uint32_t wchO = sb + (uint32_t)WCH_(jO);
            const uint32_t swA0 = swz128(a_ro0 + (uint32_t)toff * 128);
            const uint32_t swA1 = swz128(a_ro1 + (uint32_t)toff * 128);

            const float* wjE = we_s + jE * 128;
            const float* wjO = we_s + jO * 128;
            uint32_t e0 = cvt_f16x2(wjE[prow],      wjE[prow]);
            uint32_t e1 = cvt_f16x2(wjE[prow + 8],  wjE[prow + 8]);
            uint32_t e2 = cvt_f16x2(wjE[prow + 16], wjE[prow + 16]);
            uint32_t e3 = cvt_f16x2(wjE[prow + 24], wjE[prow + 24]);
            uint32_t o0 = cvt_f16x2(wjO[prow],      wjO[prow]);
            uint32_t o1 = cvt_f16x2(wjO[prow + 8],  wjO[prow + 8]);
            uint32_t o2 = cvt_f16x2(wjO[prow + 16], wjO[prow + 16]);
            uint32_t o3 = cvt_f16x2(wjO[prow + 24], wjO[prow + 24]);

            #pragma unroll
            for (int k16 = 0; k16 < 4; ++k16) {
                const uint32_t kb = (uint32_t)k16 * 32;
                uint32_t a0[4], a1[4], be[4], bo[4], s[4];
                ldsm_x4(a0, xhi_b + (swA0 ^ kb));
                ldsm_x4(a1, xhi_b + (swA1 ^ kb));
                ldsm_x4(be, wchE + (sw_b ^ kb));
                ldsm_x4(bo, wchO + (sw_b ^ kb));
                // even tap
                s[0] = hmul2u(a0[0], e0); s[2] = hmul2u(a0[2], e0);
                s[1] = hmul2u(a0[1], e1); s[3] = hmul2u(a0[3], e1);
                mma_f16(accE + 0, s, be[0], be[2]);
                mma_f16(accE + 4, s, be[1], be[3]);
                s[0] = hmul2u(a1[0], e2); s[2] = hmul2u(a1[2], e2);
                s[1] = hmul2u(a1[1], e3); s[3] = hmul2u(a1[3], e3);
                mma_f16(accE + 8,  s, be[0], be[2]);
                mma_f16(accE + 12, s, be[1], be[3]);
                // odd tap (same A raw fragments)
                s[0] = hmul2u(a0[0], o0); s[2] = hmul2u(a0[2], o0);
                s[1] = hmul2u(a0[1], o1); s[3] = hmul2u(a0[3], o1);
                mma_f16(accO + 0, s, bo[0], bo[2]);
                mma_f16(accO + 4, s, bo[1], bo[3]);
                s[0] = hmul2u(a1[0], o2); s[2] = hmul2u(a1[2], o2);
                s[1] = hmul2u(a1[1], o3); s[3] = hmul2u(a1[3], o3);
                mma_f16(accO + 8,  s, bo[0], bo[2]);
                mma_f16(accO + 12, s, bo[1], bo[3]);
            }
        }

        // ---- epilogue: coalesced float2(even, odd) per (o, p); no end sync ----
        {
            float* obB = out + (size_t)b * 64 * LOUT_;
            #pragma unroll
            for (int h = 0; h < 2; ++h) {
                #pragma unroll
                for (int jn = 0; jn < 2; ++jn) {
                    #pragma unroll
                    for (int q = 0; q < 4; ++q) {
                        const int i = h * 8 + jn * 4 + q;
                        const int p = pbase + h * 16 + (lane >> 2) + (q >> 1) * 8;
                        const int o = obase + jn * 8 + (lane & 3) * 2 + (q & 1);
                        *(float2*)(obB + (size_t)o * LOUT_ + 2 * (size_t)(p0 + p)) =
                            make_float2(accE[i], accO[i]);
                    }
                }
            }
        }
        // end sync removed: next tile's first barrier orders XH/we/xs reuse
    }
}

extern "C" void kernel_launch(void* const* d_in, const int* in_sizes, int n_in,
                              void* d_out, int out_size) {
    const float* x      = (const float*)d_in[0];
    const float* coords = (const float*)d_in[1];
    const float* sigma  = (const float*)d_in[2];
    const float* weight = (const float*)d_in[3];
    float* out = (float*)d_out;
    (void)in_sizes; (void)n_in; (void)out_size;

    cudaFuncSetAttribute(wct_mma_kernel, cudaFuncAttributeMaxDynamicSharedMemorySize, SMEM_BYTES);

    int dev = 0, sms = 148;
    cudaGetDevice(&dev);
    cudaDeviceGetAttribute(&sms, cudaDevAttrMultiProcessorCount, dev);
    if (sms <= 0) sms = 148;

    wct_mma_kernel<<<sms, THREADS_, SMEM_BYTES>>>(x, coords, sigma, weight, out);
}

// round 17
// speedup vs baseline: 1.0057x; 1.0057x over previous
#include <cuda_runtime.h>
#include <cuda_fp16.h>
#include <cstdint>

// WeightedConvTranspose via mma.sync (fp16 m16n8k16, fp32 accum).
// R17 = R16 + division-free staging:
//   interior x staging: c = tid>>3, chunks ch = (tid&7)+8k fully unrolled,
//   constant-stride addresses (no idx/66, idx%66 per op). Coords: one-iteration
//   guarded form. Edge tiles (16/1024) keep the generic clamped path.

#define B_       8
#define NIN_     16384
#define LOUT_    32768
#define PT_      128
#define THREADS_ 512
#define TILES_   (B_ * (NIN_ / PT_))   // 1024

#define XSP_     134                    // x stage pitch (floats), conflict-free transpose
#define CSP_     264

// ---- SMEM layout (bytes) ----
#define OFF_W    0                      // 9 chunks x 8192 (fp16 W) = 73728
#define WCH_(j)  (OFF_W + (j) * 8192)
#define OFF_XHI  73728                  // XH: 132 rows x 128B = 16896 (single buffer)
#define OFF_XS   90624                  // 2 bufs x 64*134*4 = 2 x 34304
#define OFF_CSB  159232                 // 2 bufs x 3*264*4  = 2 x 3168
#define OFF_WE   165568                 // 9*128*4 = 4608 (single buffer)
#define SMEM_BYTES 170176

static __device__ __forceinline__ uint32_t smem_u32(const void* p) {
    uint32_t a;
    asm("{ .reg .u64 t; cvta.to.shared.u64 t, %1; cvt.u32.u64 %0, t; }" : "=r"(a) : "l"(p));
    return a;
}
static __device__ __forceinline__ uint32_t swz128(uint32_t off) {
    return off ^ ((off >> 3) & 0x70);
}
static __device__ __forceinline__ uint32_t cvt_f16x2(float a, float b) {
    uint32_t r;
    asm("cvt.rn.f16x2.f32 %0, %1, %2;" : "=r"(r) : "f"(b), "f"(a));
    return r;
}
static __device__ __forceinline__ uint32_t hmul2u(uint32_t a, uint32_t w) {
    uint32_t r;
    asm("mul.rn.f16x2 %0, %1, %2;" : "=r"(r) : "r"(a), "r"(w));
    return r;
}
static __device__ __forceinline__ void ldsm_x4(uint32_t* r, uint32_t addr) {
    asm volatile("ldmatrix.sync.aligned.m8n8.x4.shared.b16 {%0,%1,%2,%3}, [%4];"
                 : "=r"(r[0]), "=r"(r[1]), "=r"(r[2]), "=r"(r[3]) : "r"(addr));
}
static __device__ __forceinline__ void mma_f16(float* d, const uint32_t* a,
                                               uint32_t b0, uint32_t b1) {
    asm volatile("mma.sync.aligned.m16n8k16.row.col.f32.f16.f16.f32 "
                 "{%0,%1,%2,%3}, {%4,%5,%6,%7}, {%8,%9}, {%0,%1,%2,%3};"
                 : "+f"(d[0]), "+f"(d[1]), "+f"(d[2]), "+f"(d[3])
                 : "r"(a[0]), "r"(a[1]), "r"(a[2]), "r"(a[3]), "r"(b0), "r"(b1));
}
static __device__ __forceinline__ void cp8(uint32_t dst, const float* src, int valid) {
    asm volatile("cp.async.ca.shared.global [%0], [%1], 8, %2;"
                 :: "r"(dst), "l"(src), "r"(valid) : "memory");
}
static __device__ __forceinline__ void cp8f(uint32_t dst, const float* src) {
    asm volatile("cp.async.ca.shared.global [%0], [%1], 8;"
                 :: "r"(dst), "l"(src) : "memory");
}
static __device__ __forceinline__ void cp16(uint32_t dst, const float* src, int valid) {
    asm volatile("cp.async.ca.shared.global [%0], [%1], 16, %2;"
                 :: "r"(dst), "l"(src), "r"(valid) : "memory");
}
static __device__ __forceinline__ void cp16f(uint32_t dst, const float* src) {
    asm volatile("cp.async.ca.shared.global [%0], [%1], 16;"
                 :: "r"(dst), "l"(src) : "memory");
}

__global__ void __launch_bounds__(THREADS_, 1)
wct_mma_kernel(const float* __restrict__ x, const float* __restrict__ coords,
               const float* __restrict__ sigma, const float* __restrict__ weight,
               float* __restrict__ out) {
    extern __shared__ char smem[];
    const uint32_t sb = smem_u32(smem);
    const int tid  = threadIdx.x;
    const int wid  = tid >> 5;
    const int lane = tid & 31;

    float* we_s = (float*)(smem + OFF_WE);

    // ---- one-time W (single fp16): chunk j = W[o][c] for tap j, SW128 rows ----
    for (int idx = tid; idx < 64 * 64 * 9; idx += THREADS_) {
        int j  = idx % 9;
        int oc = idx / 9;
        int c  = oc & 63;
        int o  = oc >> 6;
        __half h = __float2half_rn(weight[oc * 9 + j]);
        uint32_t bo = swz128((uint32_t)o * 128 + (uint32_t)c * 2);
        *(__half*)(smem + WCH_(j) + bo) = h;
    }
    const float rsig = 1.0f / sigma[0];

    // warp tile: 16 warps = 4 p-groups (32p) x 4 o-groups (16o), both parities
    const int on  = wid & 3;
    const int pg  = wid >> 2;
    const int pbase = pg * 32;
    const int obase = on * 16;
    const int prow  = pbase + (lane >> 2);

    const uint32_t a_ro0 = (uint32_t)(pbase + (lane & 15)) * 128 + (uint32_t)(lane >> 4) * 16;
    const uint32_t a_ro1 = a_ro0 + 16 * 128;
    const uint32_t b_ro  = (uint32_t)(obase + (lane & 15)) * 128 + (uint32_t)(lane >> 4) * 16;
    const uint32_t sw_b  = swz128(b_ro);     // toff-invariant; ^kb per k16

    // phase-2 convert lane mapping
    const int bp  = wid * 8 + (lane >> 2);
    const int bc0 = lane & 3;

    // staging lane mapping (division-free interior path)
    const int sc = tid >> 3;      // x row 0..63
    const int l8 = tid & 7;

    // ---- cp.async issue for one tile into buffer 'buf' ----
    auto issue_cp = [&](int ti, int buf) {
        const int b  = ti >> 7;
        const int p0 = (ti & 127) * PT_;
        const uint32_t xsd = sb + OFF_XS + (uint32_t)buf * 34304u;
        const uint32_t csd = sb + OFF_CSB + (uint32_t)buf * 3168u;
        if (p0 >= 2 && p0 <= NIN_ - 132) {
            // interior fast path: fixed row per thread, constant-stride chunks
            const float* src = x + (size_t)b * 64 * NIN_ + (size_t)sc * NIN_ + (p0 - 2) + 2 * l8;
            uint32_t dst = xsd + (uint32_t)(sc * XSP_ + 2 * l8) * 4u;
            #pragma unroll
            for (int k = 0; k < 8; ++k)
                cp8f(dst + (uint32_t)k * 64u, src + 16 * k);
            if (l8 < 2)
                cp8f(dst + 8u * 64u, src + 128);
            // coords: 3 rows x 66 chunks of 4 floats, one iteration per thread
            if (tid < 198) {
                int d  = tid / 66;
                int ch = tid - d * 66;
                cp16f(csd + (uint32_t)(d * CSP_ + 4 * ch) * 4u,
                      coords + (size_t)b * 3 * LOUT_ + (size_t)d * LOUT_ + (2 * p0 - 4) + 4 * ch);
            }
        } else {
            // edge path (16/1024 tiles): zfill OOB via src-size
            for (int idx = tid; idx < 64 * 66; idx += THREADS_) {
                int c  = idx / 66;
                int ch = idx - c * 66;
                int xi0 = 2 * ch;
                int g0  = p0 - 2 + xi0;
                int rem = NIN_ - g0;
                int valid = (g0 < 0) ? 0 : (rem >= 2 ? 8 : (rem == 1 ? 4 : 0));
                int gc  = g0 < 0 ? 0 : (g0 > NIN_ - 2 ? NIN_ - 2 : g0);
                cp8(xsd + (uint32_t)(c * XSP_ + xi0) * 4u,
                    x + (size_t)b * 64 * NIN_ + (size_t)c * NIN_ + gc, valid);
            }
            for (int idx = tid; idx < 3 * 66; idx += THREADS_) {
                int d  = idx / 66;
                int ch = idx - d * 66;
                int k0 = 4 * ch;
                int g0 = 2 * p0 - 4 + k0;
                int rem = LOUT_ - g0;
                int valid = (g0 < 0) ? 0 : (rem >= 4 ? 16 : (rem > 0 ? rem * 4 : 0));
                int gc = g0 < 0 ? 0 : (g0 > LOUT_ - 4 ? LOUT_ - 4 : g0);
                cp16(csd + (uint32_t)(d * CSP_ + k0) * 4u,
                     coords + (size_t)b * 3 * LOUT_ + (size_t)d * LOUT_ + gc, valid);
            }
        }
    };

    __syncthreads();  // W ready

    if ((int)blockIdx.x < TILES_) issue_cp(blockIdx.x, 0);
    asm volatile("cp.async.commit_group;" ::: "memory");

    int it = 0;
    for (int ti = blockIdx.x; ti < TILES_; ti += gridDim.x, ++it) {
        const int buf = it & 1;
        const int b   = ti >> 7;
        const int p0  = (ti & 127) * PT_;
        const int nxt = ti + gridDim.x;

        asm volatile("cp.async.wait_group 0;" ::: "memory");  // cp(ti) done
        __syncthreads();   // cp(ti) visible; prior buffers' readers done

        if (nxt < TILES_) {
            issue_cp(nxt, buf ^ 1);
            asm volatile("cp.async.commit_group;" ::: "memory");
        }

        float* xsB  = (float*)(smem + OFF_XS + (uint32_t)buf * 34304u);
        float* cs_s = (float*)(smem + OFF_CSB + (uint32_t)buf * 3168u);

        // ---- phase 2: convert x[c][xi] -> XH[xi][c] fp16 (SW128), compute we ----
        {
            const uint32_t m = ((uint32_t)bp & 7) << 4;
            char* hbase = smem + OFF_XHI + bp * 128;
            #pragma unroll
            for (int rr = 0; rr < 4; ++rr) {
                int c0 = bc0 * 4 + rr * 16;
                float a0 = xsB[(c0 + 0) * XSP_ + bp];
                float a1 = xsB[(c0 + 1) * XSP_ + bp];
                float a2 = xsB[(c0 + 2) * XSP_ + bp];
                float a3 = xsB[(c0 + 3) * XSP_ + bp];
                uint32_t h0 = cvt_f16x2(a0, a1);
                uint32_t h1 = cvt_f16x2(a2, a3);
                uint32_t d = ((uint32_t)c0 * 2) ^ m;
                *(uint2*)(hbase + d) = make_uint2(h0, h1);
            }
            if (tid < 64) {                            // tail rows 128..131
                int row = 128 + (tid >> 4);
                int c0  = (tid & 15) * 4;
                const uint32_t m2 = ((uint32_t)row & 7) << 4;
                float a0 = xsB[(c0 + 0) * XSP_ + row];
                float a1 = xsB[(c0 + 1) * XSP_ + row];
                float a2 = xsB[(c0 + 2) * XSP_ + row];
                float a3 = xsB[(c0 + 3) * XSP_ + row];
                uint32_t h0 = cvt_f16x2(a0, a1);
                uint32_t h1 = cvt_f16x2(a2, a3);
                uint32_t d = ((uint32_t)c0 * 2) ^ m2;
                *(uint2*)(smem + OFF_XHI + row * 128 + d) = make_uint2(h0, h1);
            }
        }
        // radial weights we[j][p] for l = 2p + (j&1)
        for (int idx = tid; idx < 9 * 128; idx += THREADS_) {
            int j = idx >> 7;
            int p = idx & 127;
            int pr = j & 1;
            int kt = 2 * p + pr + j;
            int kc = 2 * p + pr + 4;
            float dx = cs_s[kt] - cs_s[kc];
            float dy = cs_s[CSP_ + kt] - cs_s[CSP_ + kc];
            float dz = cs_s[2 * CSP_ + kt] - cs_s[2 * CSP_ + kc];
            float nn = sqrtf(fmaf(dx, dx, fmaf(dy, dy, dz * dz)));
            we_s[idx] = fmaxf(1.0f - nn * rsig, 0.0f);
        }
        __syncthreads();

        // ---- phase 3: toff loop; tap pair (2t-1, 2t) shares A-fragments ----
        float accE[16], accO[16];
        #pragma unroll
        for (int i = 0; i < 16; ++i) { accE[i] = 0.0f; accO[i] = 0.0f; }

        const uint32_t xhi_b = sb + OFF_XHI;

        // peel toff = 0 (even tap j=0 only)
        {
            const float* wj = we_s;                    // j = 0
            uint32_t w0 = cvt_f16x2(wj[prow],      wj[prow]);
            uint32_t w1 = cvt_f16x2(wj[prow + 8],  wj[prow + 8]);
            uint32_t w2 = cvt_f16x2(wj[prow + 16], wj[prow + 16]);
            uint32_t w3 = cvt_f16x2(wj[prow + 24], wj[prow + 24]);
            const uint32_t wchE = sb + (uint32_t)WCH_(0);
            const uint32_t swA0 = swz128(a_ro0);
            const uint32_t swA1 = swz128(a_ro1);
            #pragma unroll
            for (int k16 = 0; k16 < 4; ++k16) {
                const uint32_t kb = (uint32_t)k16 * 32;
                uint32_t a0[4], a1[4], be[4], s[4];
                ldsm_x4(a0, xhi_b + (swA0 ^ kb));
                ldsm_x4(a1, xhi_b + (swA1 ^ kb));
                ldsm_x4(be, wchE + (sw_b ^ kb));
                s[0] = hmul2u(a0[0], w0); s[2] = hmul2u(a0[2], w0);
                s[1] = hmul2u(a0[1], w1); s[3] = hmul2u(a0[3], w1);
                mma_f16(accE + 0, s, be[0], be[2]);
                mma_f16(accE + 4, s, be[1], be[3]);
                s[0] = hmul2u(a1[0], w2); s[2] = hmul2u(a1[2], w2);
                s[1] = hmul2u(a1[1], w3); s[3] = hmul2u(a1[3], w3);
                mma_f16(accE + 8,  s, be[0], be[2]);
                mma_f16(accE + 12, s, be[1], be[3]);
            }
        }

        #pragma unroll 1
        for (int toff = 1; toff < 5; ++toff) {
            const int jE = 2 * toff;        // even tap
            const int jO = 2 * toff - 1;    // odd tap (same toff)
            const uint32_t wchE = sb + (uint32_t)WCH_(jE);
            const uint32_t wchO = sb + (uint32_t)WCH_(jO);
            const uint32_t swA0 = swz128(a_ro0 + (uint32_t)toff * 128);
            const uint32_t swA1 = swz128(a_ro1 + (uint32_t)toff * 128);

            const float* wjE = we_s + jE * 128;
            const float* wjO = we_s + jO * 128;
            uint32_t e0 = cvt_f16x2(wjE[prow],      wjE[prow]);
            uint32_t e1 = cvt_f16x2(wjE[prow + 8],  wjE[prow + 8]);
            uint32_t e2 = cvt_f16x2(wjE[prow + 16], wjE[prow + 16]);
            uint32_t e3 = cvt_f16x2(wjE[prow + 24], wjE[prow + 24]);
            uint32_t o0 = cvt_f16x2(wjO[prow],      wjO[prow]);
            uint32_t o1 = cvt_f16x2(wjO[prow + 8],  wjO[prow + 8]);
            uint32_t o2 = cvt_f16x2(wjO[prow + 16], wjO[prow + 16]);
            uint32_t o3 = cvt_f16x2(wjO[prow + 24], wjO[prow + 24]);

            #pragma unroll
            for (int k16 = 0; k16 < 4; ++k16) {
                const uint32_t kb = (uint32_t)k16 * 32;
                uint32_t a0[4], a1[4], be[4], bo[4], s[4];
                ldsm_x4(a0, xhi_b + (swA0 ^ kb));
                ldsm_x4(a1, xhi_b + (swA1 ^ kb));
                ldsm_x4(be, wchE + (sw_b ^ kb));
                ldsm_x4(bo, wchO + (sw_b ^ kb));
                // even tap
                s[0] = hmul2u(a0[0], e0); s[2] = hmul2u(a0[2], e0);
                s[1] = hmul2u(a0[1], e1); s[3] = hmul2u(a0[3], e1);
                mma_f16(accE + 0, s, be[0], be[2]);
                mma_f16(accE + 4, s, be[1], be[3]);
                s[0] = hmul2u(a1[0], e2); s[2] = hmul2u(a1[2], e2);
                s[1] = hmul2u(a1[1], e3); s[3] = hmul2u(a1[3], e3);
                mma_f16(accE + 8,  s, be[0], be[2]);
                mma_f16(accE + 12, s, be[1], be[3]);
                // odd tap (same A raw fragments)
                s[0] = hmul2u(a0[0], o0); s[2] = hmul2u(a0[2], o0);
                s[1] = hmul2u(a0[1], o1); s[3] = hmul2u(a0[3], o1);
                mma_f16(accO + 0, s, bo[0], bo[2]);
                mma_f16(accO + 4, s, bo[1], bo[3]);
                s[0] = hmul2u(a1[0], o2); s[2] = hmul2u(a1[2], o2);
                s[1] = hmul2u(a1[1], o3); s[3] = hmul2u(a1[3], o3);
                mma_f16(accO + 8,  s, bo[0], bo[2]);
                mma_f16(accO + 12, s, bo[1], bo[3]);
            }
        }

        // ---- epilogue: coalesced float2(even, odd) per (o, p); no end sync ----
        {
            float* obB = out + (size_t)b * 64 * LOUT_;
            #pragma unroll
            for (int h = 0; h < 2; ++h) {
                #pragma unroll
                for (int jn = 0; jn < 2; ++jn) {
                    #pragma unroll
                    for (int q = 0; q < 4; ++q) {
                        const int i = h * 8 + jn * 4 + q;
                        const int p = pbase + h * 16 + (lane >> 2) + (q >> 1) * 8;
                        const int o = obase + jn * 8 + (lane & 3) * 2 + (q & 1);
                        *(float2*)(obB + (size_t)o * LOUT_ + 2 * (size_t)(p0 + p)) =
                            make_float2(accE[i], accO[i]);
                    }
                }
            }
        }
        // end sync removed: next tile's first barrier orders XH/we/xs reuse
    }
}

extern "C" void kernel_launch(void* const* d_in, const int* in_sizes, int n_in,
                              void* d_out, int out_size) {
    const float* x      = (const float*)d_in[0];
    const float* coords = (const float*)d_in[1];
    const float* sigma  = (const float*)d_in[2];
    const float* weight = (const float*)d_in[3];
    float* out = (float*)d_out;
    (void)in_sizes; (void)n_in; (void)out_size;

    cudaFuncSetAttribute(wct_mma_kernel, cudaFuncAttributeMaxDynamicSharedMemorySize, SMEM_BYTES);

    int dev = 0, sms = 148;
    cudaGetDevice(&dev);
    cudaDeviceGetAttribute(&sms, cudaDevAttrMultiProcessorCount, dev);
    if (sms <= 0) sms = 148;

    wct_mma_kernel<<<sms, THREADS_, SMEM_BYTES>>>(x, coords, sigma, weight, out);
}